// round 17
// baseline (speedup 1.0000x reference)
#include <cuda_runtime.h>
#include <cuda_bf16.h>
#include <cstdint>

// RBF kernel matrix: out[i,j] = v * exp(cross_ij - hx_i - hy_j)
// cross via classic mma.sync m16n8k16 bf16, 3-term hi/lo split
// (hi*hi + hi*lo + lo*hi). N = M = 8192, D = 64. Output fp32 [N, M].
// R15: intra-warp software pipelining. CTA = 128 thr (4 warps of 64x32),
// owns a 128x128 tile as two 64x128 subtiles. All operands prefetched
// once (no mid-kernel syncs). Epilogue of subtile 0 is interleaved
// k-chunk-by-k-chunk into the mainloop of subtile 1 so MUFU/STG issue in
// the HMMA shadow. Y tile shared by both subtiles (halves Y traffic).

#define NROWS 8192
#define MROWS 8192
#define DDIM  64

// ---------------- device scratch (allocation-free rule) ----------------
__device__ float g_invl[DDIM];
__device__ float g_v;
__device__ float g_lv;                            // log2(v)
__device__ float g_hxn[NROWS];                    // 0.5*||Xl_i||^2
__device__ float g_hyn[MROWS];                    // 0.5*||X2l_j||^2
__device__ __nv_bfloat16 g_Xhi[NROWS * DDIM];
__device__ __nv_bfloat16 g_Xlo[NROWS * DDIM];
__device__ __nv_bfloat16 g_Yhi[MROWS * DDIM];
__device__ __nv_bfloat16 g_Ylo[MROWS * DDIM];

// ---------------- helpers ----------------
__device__ __forceinline__ uint32_t smem_u32(const void* p) {
    uint32_t a;
    asm("{ .reg .u64 t; cvta.to.shared.u64 t, %1; cvt.u32.u64 %0, t; }"
        : "=r"(a) : "l"(p));
    return a;
}

__device__ __forceinline__ void ldsm_x4(uint32_t& r0, uint32_t& r1,
                                        uint32_t& r2, uint32_t& r3,
                                        uint32_t addr) {
    asm volatile("ldmatrix.sync.aligned.m8n8.x4.shared.b16 {%0,%1,%2,%3}, [%4];"
                 : "=r"(r0), "=r"(r1), "=r"(r2), "=r"(r3) : "r"(addr));
}

__device__ __forceinline__ void mma_bf16(float* c, const uint32_t* a,
                                         uint32_t b0, uint32_t b1) {
    asm volatile(
        "mma.sync.aligned.m16n8k16.row.col.f32.bf16.bf16.f32 "
        "{%0,%1,%2,%3}, {%4,%5,%6,%7}, {%8,%9}, {%0,%1,%2,%3};"
        : "+f"(c[0]), "+f"(c[1]), "+f"(c[2]), "+f"(c[3])
        : "r"(a[0]), "r"(a[1]), "r"(a[2]), "r"(a[3]), "r"(b0), "r"(b1));
}

__device__ __forceinline__ float fexp2(float x) {
    float r;
    asm("ex2.approx.f32 %0, %1;" : "=f"(r) : "f"(x));
    return r;
}

#define CP_ASYNC16(dst, src) \
    asm volatile("cp.async.cg.shared.global [%0], [%1], 16;" \
                 :: "r"(dst), "l"(src) : "memory")
#define CP_COMMIT() asm volatile("cp.async.commit_group;" ::: "memory")
#define CP_WAIT0()  asm volatile("cp.async.wait_group 0;" ::: "memory")

// ---------------------------------------------------------------------------
// Prep: softplus params, bf16 hi/lo split of scaled rows, half squared norms
// ---------------------------------------------------------------------------
__global__ void prep_kernel(const float* __restrict__ X,
                            const float* __restrict__ X2,
                            const float* __restrict__ ls,
                            const float* __restrict__ var) {
    __shared__ float invl_s[DDIM];
    int t = threadIdx.x;
    if (t < DDIM) {
        float r = ls[t];
        float l = fmaxf(r, 0.0f) + log1pf(expf(-fabsf(r)));
        float il = 1.0f / l;
        invl_s[t] = il;
        if (blockIdx.x == 0) g_invl[t] = il;
    }
    if (blockIdx.x == 0 && t == 64) {
        float r = var[0];
        float v = fmaxf(r, 0.0f) + log1pf(expf(-fabsf(r)));
        g_v = v;
        g_lv = log2f(v);
    }
    __syncthreads();

    int warp = t >> 5, lane = t & 31;
    int nwarps = blockDim.x >> 5;
    for (int row = blockIdx.x * nwarps + warp; row < NROWS + MROWS;
         row += gridDim.x * nwarps) {
        const float* src;
        __nv_bfloat16 *hi, *lo;
        int r;
        bool isX = (row < NROWS);
        if (isX) { r = row;         src = X  + (size_t)r * DDIM; hi = g_Xhi; lo = g_Xlo; }
        else     { r = row - NROWS; src = X2 + (size_t)r * DDIM; hi = g_Yhi; lo = g_Ylo; }
        float s = 0.0f;
        #pragma unroll
        for (int j = 0; j < 2; j++) {
            int d = lane + 32 * j;
            float xl = src[d] * invl_s[d];
            __nv_bfloat16 bh = __float2bfloat16(xl);
            __nv_bfloat16 bl = __float2bfloat16(xl - __bfloat162float(bh));
            hi[(size_t)r * DDIM + d] = bh;
            lo[(size_t)r * DDIM + d] = bl;
            s = fmaf(xl, xl, s);
        }
        #pragma unroll
        for (int off = 16; off; off >>= 1)
            s += __shfl_xor_sync(0xffffffffu, s, off);
        if (lane == 0) {
            if (isX) g_hxn[r] = 0.5f * s;
            else     g_hyn[r] = 0.5f * s;
        }
    }
}

// ---------------------------------------------------------------------------
// Main kernel. CTA = 128 threads (4 warps), 128x128 output tile processed
// as two 64x128 subtiles. Each warp: 64x32 per subtile via mma m16n8k16
// (4 mt x 4 nt x 3 terms x 4 k-chunks). Smem: HX/HY norms + X0,X1 (16KB
// each, hi+lo) + Y (32KB, hi+lo), all prefetched in one cp.async group.
// 16B-chunk XOR swizzle phys_chunk = c ^ (row & 7) -> ldmatrix
// conflict-free.
// ---------------------------------------------------------------------------
#define SMEM_HX    0                   // 128 floats: hx*L2E - log2(v)
#define SMEM_HY    512                 // 128 floats: hy*L2E
#define SMEM_X0    1024
#define XT_BYTES   8192                // 64 rows * 128B (one of hi/lo)
#define SMEM_X1    (SMEM_X0 + 2 * XT_BYTES)
#define SMEM_Y     (SMEM_X1 + 2 * XT_BYTES)
#define YT_BYTES   16384               // 128 rows * 128B
#define SMEM_TOTAL (SMEM_Y + 2 * YT_BYTES)   // 66560 B

// One k-chunk of the 3-term mainloop: 12 LDSM.x4 + 48 HMMA.
__device__ __forceinline__ void mma_kchunk(uint32_t sXhi, uint32_t sYhi,
                                           uint32_t rowA, uint32_t rowB,
                                           uint32_t k, float acc[4][4][4]) {
    uint32_t bh[2][4], bl[2][4], ah[4][4], al[4][4];
    #pragma unroll
    for (int bp = 0; bp < 2; bp++) {
        ldsm_x4(bh[bp][0], bh[bp][1], bh[bp][2], bh[bp][3],
                sYhi + rowB + bp * 2048 + k);
        ldsm_x4(bl[bp][0], bl[bp][1], bl[bp][2], bl[bp][3],
                sYhi + YT_BYTES + rowB + bp * 2048 + k);
    }
    #pragma unroll
    for (int mt = 0; mt < 4; mt++)
        ldsm_x4(ah[mt][0], ah[mt][1], ah[mt][2], ah[mt][3],
                sXhi + rowA + mt * 2048 + k);
    // term hi*hi
    #pragma unroll
    for (int mt = 0; mt < 4; mt++) {
        mma_bf16(acc[mt][0], ah[mt], bh[0][0], bh[0][2]);
        mma_bf16(acc[mt][1], ah[mt], bh[0][1], bh[0][3]);
        mma_bf16(acc[mt][2], ah[mt], bh[1][0], bh[1][2]);
        mma_bf16(acc[mt][3], ah[mt], bh[1][1], bh[1][3]);
    }
    // load A-lo while hi*lo MMAs run
    #pragma unroll
    for (int mt = 0; mt < 4; mt++)
        ldsm_x4(al[mt][0], al[mt][1], al[mt][2], al[mt][3],
                sXhi + XT_BYTES + rowA + mt * 2048 + k);
    // term hi*lo
    #pragma unroll
    for (int mt = 0; mt < 4; mt++) {
        mma_bf16(acc[mt][0], ah[mt], bl[0][0], bl[0][2]);
        mma_bf16(acc[mt][1], ah[mt], bl[0][1], bl[0][3]);
        mma_bf16(acc[mt][2], ah[mt], bl[1][0], bl[1][2]);
        mma_bf16(acc[mt][3], ah[mt], bl[1][1], bl[1][3]);
    }
    // term lo*hi
    #pragma unroll
    for (int mt = 0; mt < 4; mt++) {
        mma_bf16(acc[mt][0], al[mt], bh[0][0], bh[0][2]);
        mma_bf16(acc[mt][1], al[mt], bh[0][1], bh[0][3]);
        mma_bf16(acc[mt][2], al[mt], bh[1][0], bh[1][2]);
        mma_bf16(acc[mt][3], al[mt], bh[1][1], bh[1][3]);
    }
}

// Epilogue for one 16-row mt group (32 cols): 16 MUFU + 8 STG.64 per thread.
__device__ __forceinline__ void epi_mt(float c[4][4], int xrow0, int y0,
                                       int nbase, int g, int n2,
                                       float hx0, float hx1,
                                       const float* HY, float L2E,
                                       float* __restrict__ out) {
    #pragma unroll
    for (int nt = 0; nt < 4; nt++) {
        const int cc = nbase + nt * 8 + n2;
        const float hy0 = HY[cc];
        const float hy1 = HY[cc + 1];
        float2 o0, o1;
        o0.x = fexp2(fmaf(c[nt][0], L2E, -hx0 - hy0));
        o0.y = fexp2(fmaf(c[nt][1], L2E, -hx0 - hy1));
        o1.x = fexp2(fmaf(c[nt][2], L2E, -hx1 - hy0));
        o1.y = fexp2(fmaf(c[nt][3], L2E, -hx1 - hy1));
        *(float2*)(out + (size_t)xrow0 * MROWS + y0 + cc)       = o0;
        *(float2*)(out + (size_t)(xrow0 + 8) * MROWS + y0 + cc) = o1;
    }
}

__global__ void __launch_bounds__(128, 3)
rbf_mma_kernel(float* __restrict__ out) {
    extern __shared__ char smem[];
    const uint32_t sb = smem_u32(smem);
    const int t = threadIdx.x;
    const int wid = t >> 5;
    const int lane = t & 31;

    const int x0 = blockIdx.y * 128;      // X rows (two 64-row subtiles)
    const int y0 = blockIdx.x * 128;      // X2 rows (output cols)

    const float L2E = 1.4426950408889634f;
    const float lv = g_lv;

    const uint32_t sX0 = sb + SMEM_X0;
    const uint32_t sX1 = sb + SMEM_X1;
    const uint32_t sY  = sb + SMEM_Y;

    // Prologue: everything in one cp.async group (64 KB total).
    {
        const uint4* sx0h = (const uint4*)(g_Xhi + (size_t)x0 * DDIM);
        const uint4* sx0l = (const uint4*)(g_Xlo + (size_t)x0 * DDIM);
        const uint4* sx1h = (const uint4*)(g_Xhi + (size_t)(x0 + 64) * DDIM);
        const uint4* sx1l = (const uint4*)(g_Xlo + (size_t)(x0 + 64) * DDIM);
        #pragma unroll
        for (int i = 0; i < 4; i++) {          // 512 chunks each
            int id = t + i * 128;
            int row = id >> 3, c = id & 7;
            uint32_t sw = (uint32_t)row * 128 + (uint32_t)((c ^ (row & 7)) * 16);
            CP_ASYNC16(sX0 + sw, sx0h + id);
            CP_ASYNC16(sX0 + XT_BYTES + sw, sx0l + id);
            CP_ASYNC16(sX1 + sw, sx1h + id);
            CP_ASYNC16(sX1 + XT_BYTES + sw, sx1l + id);
        }
        const uint4* syh = (const uint4*)(g_Yhi + (size_t)y0 * DDIM);
        const uint4* syl = (const uint4*)(g_Ylo + (size_t)y0 * DDIM);
        #pragma unroll
        for (int i = 0; i < 8; i++) {          // 1024 chunks each
            int id = t + i * 128;
            int row = id >> 3, c = id & 7;
            uint32_t sw = (uint32_t)row * 128 + (uint32_t)((c ^ (row & 7)) * 16);
            CP_ASYNC16(sY + sw, syh + id);
            CP_ASYNC16(sY + YT_BYTES + sw, syl + id);
        }
        CP_COMMIT();
    }

    // Norm tiles (pre-scaled for folded epilogue)
    ((float*)(smem + SMEM_HX))[t] = g_hxn[x0 + t] * L2E - lv;
    ((float*)(smem + SMEM_HY))[t] = g_hyn[y0 + t] * L2E;

    CP_WAIT0();
    __syncthreads();

    const int nbase = wid * 32;           // warp's 32 output cols

    // ldmatrix per-lane addressing (subtile-invariant)
    const int lrow = lane & 15;
    const int lhalf = lane >> 4;
    const int lsw = lrow & 7;
    const uint32_t rowA = (uint32_t)lrow * 128;
    const uint32_t rowB = (uint32_t)(nbase + lrow) * 128;
    uint32_t kc[4];
    #pragma unroll
    for (int kb = 0; kb < 4; kb++)
        kc[kb] = (uint32_t)(((kb * 2 + lhalf) ^ lsw) * 16);

    const int g = lane >> 2;
    const int n2 = (lane & 3) * 2;
    const float* HX = (const float*)(smem + SMEM_HX);
    const float* HY = (const float*)(smem + SMEM_HY);

    float acc1[4][4][4], acc2[4][4][4];
    #pragma unroll
    for (int mt = 0; mt < 4; mt++)
        #pragma unroll
        for (int nt = 0; nt < 4; nt++)
            #pragma unroll
            for (int f = 0; f < 4; f++) {
                acc1[mt][nt][f] = 0.0f;
                acc2[mt][nt][f] = 0.0f;
            }

    // Phase 1: mainloop subtile 0
    #pragma unroll
    for (int kb = 0; kb < 4; kb++)
        mma_kchunk(sX0, sY, rowA, rowB, kc[kb], acc1);

    // Phase 2: mainloop subtile 1 interleaved with epilogue of subtile 0.
    // Each k-chunk (48 HMMA) covers one mt-quarter of epilogue-A
    // (16 MUFU + 8 STG per thread) — independent instruction streams.
    #pragma unroll
    for (int kb = 0; kb < 4; kb++) {
        mma_kchunk(sX1, sY, rowA, rowB, kc[kb], acc2);
        const int r0 = kb * 16 + g;
        epi_mt(acc1[kb], x0 + r0, y0, nbase, g, n2,
               HX[r0], HX[r0 + 8], HY, L2E, out);
    }

    // Phase 3: epilogue subtile 1
    #pragma unroll
    for (int mt = 0; mt < 4; mt++) {
        const int r0 = mt * 16 + g;
        epi_mt(acc2[mt], x0 + 64 + r0, y0, nbase, g, n2,
               HX[64 + r0], HX[64 + r0 + 8], HY, L2E, out);
    }
}

// ---------------------------------------------------------------------------
extern "C" void kernel_launch(void* const* d_in, const int* in_sizes, int n_in,
                              void* d_out, int out_size) {
    const float* X   = (const float*)d_in[0];
    const float* X2  = (const float*)d_in[1];
    const float* ls  = (const float*)d_in[2];
    const float* var = (const float*)d_in[3];
    float* out = (float*)d_out;

    prep_kernel<<<1024, 256>>>(X, X2, ls, var);

    cudaFuncSetAttribute(rbf_mma_kernel,
                         cudaFuncAttributeMaxDynamicSharedMemorySize, SMEM_TOTAL);
    dim3 grid(MROWS / 128, NROWS / 128);
    rbf_mma_kernel<<<grid, 128, SMEM_TOTAL>>>(out);
}